// round 1
// baseline (speedup 1.0000x reference)
#include <cuda_runtime.h>
#include <cuda_bf16.h>

#define H_IMG 96
#define W_IMG 96
#define C_IMG 1024
#define POOL 7
#define NUM_ROIS 600

// One CTA per (roi, py*7+px). 256 threads, each thread handles 4 channels (float4).
__global__ __launch_bounds__(256, 8)
void roi_pool_kernel(const float* __restrict__ img,
                     const int*   __restrict__ rois,
                     float*       __restrict__ out) {
    const int pos = blockIdx.x;        // 0..48
    const int roi = blockIdx.y;        // 0..599
    const int py  = pos / POOL;
    const int px  = pos % POOL;

    // roi = (x, y, w, h)
    const int4 r = __ldg(reinterpret_cast<const int4*>(rois) + roi);
    const int x = r.x;
    const int y = r.y;
    const int w = max(r.z, 1);
    const int h = max(r.w, 1);

    // TF1 resize semantics: src = dst * (in/out), align_corners=False
    const float sy = (float)h / (float)POOL;
    const float sx = (float)w / (float)POOL;
    const float in_y = (float)py * sy;
    const float in_x = (float)px * sx;
    const int y0 = (int)in_y;               // floor (nonnegative)
    const int x0 = (int)in_x;
    const int y1 = min(y0 + 1, h - 1);
    const int x1 = min(x0 + 1, w - 1);
    const float fy = in_y - (float)y0;
    const float fx = in_x - (float)x0;

    const int r0 = min(max(y + y0, 0), H_IMG - 1);
    const int r1 = min(max(y + y1, 0), H_IMG - 1);
    const int c0 = min(max(x + x0, 0), W_IMG - 1);
    const int c1 = min(max(x + x1, 0), W_IMG - 1);

    const float4* p00 = reinterpret_cast<const float4*>(img + ((size_t)r0 * W_IMG + c0) * C_IMG);
    const float4* p01 = reinterpret_cast<const float4*>(img + ((size_t)r0 * W_IMG + c1) * C_IMG);
    const float4* p10 = reinterpret_cast<const float4*>(img + ((size_t)r1 * W_IMG + c0) * C_IMG);
    const float4* p11 = reinterpret_cast<const float4*>(img + ((size_t)r1 * W_IMG + c1) * C_IMG);

    float4* o = reinterpret_cast<float4*>(out + ((size_t)roi * (POOL * POOL) + pos) * C_IMG);

    const int t = threadIdx.x;   // 0..255 -> 4 channels each

    const float4 a = __ldg(p00 + t);
    const float4 b = __ldg(p01 + t);
    const float4 c = __ldg(p10 + t);
    const float4 d = __ldg(p11 + t);

    const float w00 = (1.0f - fx) * (1.0f - fy);
    const float w01 = fx * (1.0f - fy);
    const float w10 = (1.0f - fx) * fy;
    const float w11 = fx * fy;

    float4 res;
    res.x = a.x * w00 + b.x * w01 + c.x * w10 + d.x * w11;
    res.y = a.y * w00 + b.y * w01 + c.y * w10 + d.y * w11;
    res.z = a.z * w00 + b.z * w01 + c.z * w10 + d.z * w11;
    res.w = a.w * w00 + b.w * w01 + c.w * w10 + d.w * w11;

    o[t] = res;
}

extern "C" void kernel_launch(void* const* d_in, const int* in_sizes, int n_in,
                              void* d_out, int out_size) {
    const float* img  = (const float*)d_in[0];
    const int*   rois = (const int*)d_in[1];
    float*       out  = (float*)d_out;

    dim3 grid(POOL * POOL, NUM_ROIS);
    roi_pool_kernel<<<grid, 256>>>(img, rois, out);
}

// round 2
// speedup vs baseline: 1.0107x; 1.0107x over previous
#include <cuda_runtime.h>
#include <cuda_bf16.h>

#define H_IMG 96
#define W_IMG 96
#define C_IMG 1024
#define CV    (C_IMG / 4)   // 256 float4 per pixel
#define POOL  7
#define NUM_ROIS 600

// One CTA per roi. 256 threads; thread t owns float4 channel-slot t.
// Loop over all 49 output positions, fully unrolled for MLP.
__global__ __launch_bounds__(256, 4)
void roi_pool_kernel(const float* __restrict__ img,
                     const int*   __restrict__ rois,
                     float*       __restrict__ out) {
    const int roi = blockIdx.x;

    __shared__ int   sr0[POOL], sr1[POOL];   // row offsets (in pixels)
    __shared__ int   sc0[POOL], sc1[POOL];   // col indices
    __shared__ float sfy[POOL], sfx[POOL];

    if (threadIdx.x < POOL) {
        const int4 rr = __ldg(reinterpret_cast<const int4*>(rois) + roi);
        const int x = rr.x;
        const int y = rr.y;
        const int w = max(rr.z, 1);
        const int h = max(rr.w, 1);
        const int i = threadIdx.x;

        // TF1 resize semantics: src = dst * (in/out)
        const float in_y = (float)i * ((float)h / (float)POOL);
        const float in_x = (float)i * ((float)w / (float)POOL);
        const int y0 = (int)in_y;      // floor, nonnegative
        const int x0 = (int)in_x;
        const int y1 = min(y0 + 1, h - 1);
        const int x1 = min(x0 + 1, w - 1);
        sfy[i] = in_y - (float)y0;
        sfx[i] = in_x - (float)x0;
        sr0[i] = min(max(y + y0, 0), H_IMG - 1) * W_IMG;
        sr1[i] = min(max(y + y1, 0), H_IMG - 1) * W_IMG;
        sc0[i] = min(max(x + x0, 0), W_IMG - 1);
        sc1[i] = min(max(x + x1, 0), W_IMG - 1);
    }
    __syncthreads();

    const int t = threadIdx.x;
    const float4* __restrict__ imgv = reinterpret_cast<const float4*>(img);
    float4* __restrict__ ov = reinterpret_cast<float4*>(out)
                              + (size_t)roi * (POOL * POOL) * CV + t;

    #pragma unroll
    for (int py = 0; py < POOL; ++py) {
        const float fy  = sfy[py];
        const float gy  = 1.0f - fy;
        const float4* row0 = imgv + (size_t)sr0[py] * CV + t;
        const float4* row1 = imgv + (size_t)sr1[py] * CV + t;

        #pragma unroll
        for (int px = 0; px < POOL; ++px) {
            const float fx = sfx[px];
            const int o0 = sc0[px] * CV;
            const int o1 = sc1[px] * CV;

            const float4 a = __ldg(row0 + o0);
            const float4 b = __ldg(row0 + o1);
            const float4 c = __ldg(row1 + o0);
            const float4 d = __ldg(row1 + o1);

            const float w00 = (1.0f - fx) * gy;
            const float w01 = fx * gy;
            const float w10 = (1.0f - fx) * fy;
            const float w11 = fx * fy;

            float4 res;
            res.x = a.x * w00 + b.x * w01 + c.x * w10 + d.x * w11;
            res.y = a.y * w00 + b.y * w01 + c.y * w10 + d.y * w11;
            res.z = a.z * w00 + b.z * w01 + c.z * w10 + d.z * w11;
            res.w = a.w * w00 + b.w * w01 + c.w * w10 + d.w * w11;

            ov[(py * POOL + px) * CV] = res;
        }
    }
}

extern "C" void kernel_launch(void* const* d_in, const int* in_sizes, int n_in,
                              void* d_out, int out_size) {
    const float* img  = (const float*)d_in[0];
    const int*   rois = (const int*)d_in[1];
    float*       out  = (float*)d_out;

    roi_pool_kernel<<<NUM_ROIS, 256>>>(img, rois, out);
}

// round 3
// speedup vs baseline: 1.0575x; 1.0464x over previous
#include <cuda_runtime.h>
#include <cuda_bf16.h>

#define H_IMG 96
#define W_IMG 96
#define C_IMG 1024
#define CV    (C_IMG / 4)   // 256 float4 per pixel
#define POOL  7
#define NUM_ROIS 600

// One CTA per (roi, output position). 128 threads; thread t owns float4
// channel-slots t and t+128 -> 8 independent loads in flight per thread.
__global__ __launch_bounds__(128, 8)
void roi_pool_kernel(const float* __restrict__ img,
                     const int*   __restrict__ rois,
                     float*       __restrict__ out) {
    const int pos = blockIdx.x;        // 0..48
    const int roi = blockIdx.y;        // 0..599
    const int py  = pos / POOL;
    const int px  = pos % POOL;

    // roi = (x, y, w, h)
    const int4 r = __ldg(reinterpret_cast<const int4*>(rois) + roi);
    const int x = r.x;
    const int y = r.y;
    const int w = max(r.z, 1);
    const int h = max(r.w, 1);

    // TF1 resize semantics: src = dst * (in/out), align_corners=False
    const float in_y = (float)py * ((float)h / (float)POOL);
    const float in_x = (float)px * ((float)w / (float)POOL);
    const int y0 = (int)in_y;               // floor (nonnegative)
    const int x0 = (int)in_x;
    const int y1 = min(y0 + 1, h - 1);
    const int x1 = min(x0 + 1, w - 1);
    const float fy = in_y - (float)y0;
    const float fx = in_x - (float)x0;

    const int r0 = min(max(y + y0, 0), H_IMG - 1);
    const int r1 = min(max(y + y1, 0), H_IMG - 1);
    const int c0 = min(max(x + x0, 0), W_IMG - 1);
    const int c1 = min(max(x + x1, 0), W_IMG - 1);

    const int t = threadIdx.x;   // 0..127

    const float4* __restrict__ p00 =
        reinterpret_cast<const float4*>(img + ((size_t)r0 * W_IMG + c0) * C_IMG) + t;
    const float4* __restrict__ p01 =
        reinterpret_cast<const float4*>(img + ((size_t)r0 * W_IMG + c1) * C_IMG) + t;
    const float4* __restrict__ p10 =
        reinterpret_cast<const float4*>(img + ((size_t)r1 * W_IMG + c0) * C_IMG) + t;
    const float4* __restrict__ p11 =
        reinterpret_cast<const float4*>(img + ((size_t)r1 * W_IMG + c1) * C_IMG) + t;

    float4* __restrict__ o =
        reinterpret_cast<float4*>(out + ((size_t)roi * (POOL * POOL) + pos) * C_IMG) + t;

    // 8 independent loads issued before any dependent math
    const float4 a0 = __ldg(p00);
    const float4 b0 = __ldg(p01);
    const float4 c0v = __ldg(p10);
    const float4 d0 = __ldg(p11);
    const float4 a1 = __ldg(p00 + 128);
    const float4 b1 = __ldg(p01 + 128);
    const float4 c1v = __ldg(p10 + 128);
    const float4 d1 = __ldg(p11 + 128);

    const float w00 = (1.0f - fx) * (1.0f - fy);
    const float w01 = fx * (1.0f - fy);
    const float w10 = (1.0f - fx) * fy;
    const float w11 = fx * fy;

    float4 r0v, r1v;
    r0v.x = a0.x * w00 + b0.x * w01 + c0v.x * w10 + d0.x * w11;
    r0v.y = a0.y * w00 + b0.y * w01 + c0v.y * w10 + d0.y * w11;
    r0v.z = a0.z * w00 + b0.z * w01 + c0v.z * w10 + d0.z * w11;
    r0v.w = a0.w * w00 + b0.w * w01 + c0v.w * w10 + d0.w * w11;

    r1v.x = a1.x * w00 + b1.x * w01 + c1v.x * w10 + d1.x * w11;
    r1v.y = a1.y * w00 + b1.y * w01 + c1v.y * w10 + d1.y * w11;
    r1v.z = a1.z * w00 + b1.z * w01 + c1v.z * w10 + d1.z * w11;
    r1v.w = a1.w * w00 + b1.w * w01 + c1v.w * w10 + d1.w * w11;

    o[0]   = r0v;
    o[128] = r1v;
}

extern "C" void kernel_launch(void* const* d_in, const int* in_sizes, int n_in,
                              void* d_out, int out_size) {
    const float* img  = (const float*)d_in[0];
    const int*   rois = (const int*)d_in[1];
    float*       out  = (float*)d_out;

    dim3 grid(POOL * POOL, NUM_ROIS);
    roi_pool_kernel<<<grid, 128>>>(img, rois, out);
}

// round 4
// speedup vs baseline: 1.1261x; 1.0649x over previous
#include <cuda_runtime.h>
#include <cuda_bf16.h>

#define H_IMG 96
#define W_IMG 96
#define C_IMG 1024
#define CV    (C_IMG / 4)   // 256 float4 per pixel
#define POOL  7
#define NUM_ROIS 600

// One CTA per (roi, output position). 128 threads; thread t owns float4
// channel-slots t and t+128 -> 8 independent loads in flight per thread.
// maxBlocks=16 -> full 2048-thread occupancy (R3's cap of 8 was the limiter).
__global__ __launch_bounds__(128, 16)
void roi_pool_kernel(const float* __restrict__ img,
                     const int*   __restrict__ rois,
                     float*       __restrict__ out) {
    const int pos = blockIdx.x;        // 0..48
    const int roi = blockIdx.y;        // 0..599
    const int py  = pos / POOL;
    const int px  = pos % POOL;

    // roi = (x, y, w, h)
    const int4 r = __ldg(reinterpret_cast<const int4*>(rois) + roi);
    const int x = r.x;
    const int y = r.y;
    const int w = max(r.z, 1);
    const int h = max(r.w, 1);

    // TF1 resize semantics: src = dst * (in/out), align_corners=False
    const float in_y = (float)py * ((float)h / (float)POOL);
    const float in_x = (float)px * ((float)w / (float)POOL);
    const int y0 = (int)in_y;               // floor (nonnegative)
    const int x0 = (int)in_x;
    const int y1 = min(y0 + 1, h - 1);
    const int x1 = min(x0 + 1, w - 1);
    const float fy = in_y - (float)y0;
    const float fx = in_x - (float)x0;

    const int r0 = min(max(y + y0, 0), H_IMG - 1);
    const int r1 = min(max(y + y1, 0), H_IMG - 1);
    const int c0 = min(max(x + x0, 0), W_IMG - 1);
    const int c1 = min(max(x + x1, 0), W_IMG - 1);

    const int t = threadIdx.x;   // 0..127

    const float4* __restrict__ p00 =
        reinterpret_cast<const float4*>(img + ((size_t)r0 * W_IMG + c0) * C_IMG) + t;
    const float4* __restrict__ p01 =
        reinterpret_cast<const float4*>(img + ((size_t)r0 * W_IMG + c1) * C_IMG) + t;
    const float4* __restrict__ p10 =
        reinterpret_cast<const float4*>(img + ((size_t)r1 * W_IMG + c0) * C_IMG) + t;
    const float4* __restrict__ p11 =
        reinterpret_cast<const float4*>(img + ((size_t)r1 * W_IMG + c1) * C_IMG) + t;

    float4* __restrict__ o =
        reinterpret_cast<float4*>(out + ((size_t)roi * (POOL * POOL) + pos) * C_IMG) + t;

    // 8 independent loads issued before any dependent math
    const float4 a0 = __ldg(p00);
    const float4 b0 = __ldg(p01);
    const float4 c0v = __ldg(p10);
    const float4 d0 = __ldg(p11);
    const float4 a1 = __ldg(p00 + 128);
    const float4 b1 = __ldg(p01 + 128);
    const float4 c1v = __ldg(p10 + 128);
    const float4 d1 = __ldg(p11 + 128);

    const float w00 = (1.0f - fx) * (1.0f - fy);
    const float w01 = fx * (1.0f - fy);
    const float w10 = (1.0f - fx) * fy;
    const float w11 = fx * fy;

    float4 r0v, r1v;
    r0v.x = a0.x * w00 + b0.x * w01 + c0v.x * w10 + d0.x * w11;
    r0v.y = a0.y * w00 + b0.y * w01 + c0v.y * w10 + d0.y * w11;
    r0v.z = a0.z * w00 + b0.z * w01 + c0v.z * w10 + d0.z * w11;
    r0v.w = a0.w * w00 + b0.w * w01 + c0v.w * w10 + d0.w * w11;

    r1v.x = a1.x * w00 + b1.x * w01 + c1v.x * w10 + d1.x * w11;
    r1v.y = a1.y * w00 + b1.y * w01 + c1v.y * w10 + d1.y * w11;
    r1v.z = a1.z * w00 + b1.z * w01 + c1v.z * w10 + d1.z * w11;
    r1v.w = a1.w * w00 + b1.w * w01 + c1v.w * w10 + d1.w * w11;

    o[0]   = r0v;
    o[128] = r1v;
}

extern "C" void kernel_launch(void* const* d_in, const int* in_sizes, int n_in,
                              void* d_out, int out_size) {
    const float* img  = (const float*)d_in[0];
    const int*   rois = (const int*)d_in[1];
    float*       out  = (float*)d_out;

    dim3 grid(POOL * POOL, NUM_ROIS);
    roi_pool_kernel<<<grid, 128>>>(img, rois, out);
}